// round 11
// baseline (speedup 1.0000x reference)
#include <cuda_runtime.h>
#include <cuda_bf16.h>
#include <math.h>

#define PI_D 3.14159265358979323846

#define NLAT 256
#define NLON 256
#define LMAX 128
#define MM   128
#define CIN  32
#define COUT 32
#define BATCH 8
#define BC   (BATCH*CIN)      // 256
#define J2   (2*MM)           // 256
#define ROWS_X (BC*NLAT)      // 65536
#define ROWS_L (BC*LMAX)      // 32768
#define XSTRIDE (2*LMAX*129)  // 33024

// ---------------- tables (bf16 hi/lo, K-major as MMA B operands) ----------------
__device__ float g_wq[NLAT];
__device__ __nv_bfloat16 g_Dh[256*256], g_Dl[256*256];         // fwd DFT  B[j][n]
__device__ __nv_bfloat16 g_Ih[256*256], g_Il[256*256];         // inv DFT  B[n][j]
__device__ __nv_bfloat16 g_Wh[128*128*256], g_Wl[128*128*256]; // [m][l][k] = P*wq (l<m stays 0)
__device__ __nv_bfloat16 g_Ph[128*256*128], g_Pl[128*256*128]; // [m][k][l] = P

// ---------------- activations ----------------
__device__ float g_F   [256*65536];   // [j][bc*256+k]
__device__ float g_CF  [256*32768];   // [j][bc*128+l]
__device__ float g_spec[32768*256];   // [(b,i)*128+l][j]
__device__ float g_ospec[32768*256];  // [(b,o)*128+l][j]
__device__ float g_T   [256*32768];   // [j][bo*128+l]
__device__ float g_G   [256*65536];   // [j][bo*256+k]

// ---------------- helpers ----------------
__device__ __forceinline__ unsigned smem_u32(const void* p) {
    unsigned a;
    asm("{ .reg .u64 t; cvta.to.shared.u64 t, %1; cvt.u32.u64 %0, t; }" : "=r"(a) : "l"(p));
    return a;
}
__device__ __forceinline__ unsigned pk(__nv_bfloat16 a, __nv_bfloat16 b) {
    unsigned short ua = *reinterpret_cast<unsigned short*>(&a);
    unsigned short ub = *reinterpret_cast<unsigned short*>(&b);
    return (unsigned)ua | ((unsigned)ub << 16);
}
__device__ __forceinline__ void bf16split(float v, __nv_bfloat16& h, __nv_bfloat16& l) {
    h = __float2bfloat16(v);
    l = __float2bfloat16(v - __bfloat162float(h));
}
#define LDSM4(r0, r1, r2, r3, ad)                                                   \
    asm volatile("ldmatrix.sync.aligned.m8n8.x4.shared.b16 {%0,%1,%2,%3}, [%4];"    \
                 : "=r"(r0), "=r"(r1), "=r"(r2), "=r"(r3) : "r"(ad))
#define MMA16816(c, a, b0, b1)                                                      \
    asm volatile("mma.sync.aligned.m16n8k16.row.col.f32.bf16.bf16.f32 "             \
                 "{%0,%1,%2,%3},{%4,%5,%6,%7},{%8,%9},{%0,%1,%2,%3};"               \
                 : "+f"((c)[0]), "+f"((c)[1]), "+f"((c)[2]), "+f"((c)[3])           \
                 : "r"((a)[0]), "r"((a)[1]), "r"((a)[2]), "r"((a)[3]),              \
                   "r"(b0), "r"(b1))

// ---------------- table init ----------------
__global__ void k_init_w() {
    int j = threadIdx.x;
    float S = 0.0f;
    for (int k = 1; k <= 127; k++) {
        int r = (j * k) % 255;
        S += 2.0f / (4.0f * k * k - 1.0f) * cosf(2.0f * (float)PI_D * r / 255.0f);
    }
    float c = (j == 0 || j == 255) ? 1.0f : 2.0f;
    g_wq[j] = c / 255.0f * (1.0f - S);
}

__global__ void k_init_P() {
    int m = blockIdx.x;
    int k = threadIdx.x;
    float t  = (float)(PI_D * k / 255.0);
    float ct = cosf(t), st = sinf(t);
    float w  = g_wq[k];
    float pmm = 0.28209479177387814f;
    for (int j = 1; j <= m; j++)
        pmm *= -sqrtf((2.0f * j + 1.0f) / (2.0f * j)) * st;

    __nv_bfloat16 h, l;
    float pl0 = pmm;
    {   float pw = pl0 * w;
        bf16split(pw, h, l);
        g_Wh[((size_t)m * LMAX + m) * 256 + k] = h;  g_Wl[((size_t)m * LMAX + m) * 256 + k] = l;
        bf16split(pl0, h, l);
        g_Ph[((size_t)m * 256 + k) * LMAX + m] = h;  g_Pl[((size_t)m * 256 + k) * LMAX + m] = l; }
    if (m + 1 < LMAX) {
        float pl1 = sqrtf(2.0f * m + 3.0f) * ct * pmm;
        float pw = pl1 * w;
        bf16split(pw, h, l);
        g_Wh[((size_t)m * LMAX + m + 1) * 256 + k] = h;  g_Wl[((size_t)m * LMAX + m + 1) * 256 + k] = l;
        bf16split(pl1, h, l);
        g_Ph[((size_t)m * 256 + k) * LMAX + m + 1] = h;  g_Pl[((size_t)m * 256 + k) * LMAX + m + 1] = l;
        for (int ll = m + 2; ll < LMAX; ll++) {
            float dl = (float)ll, dm = (float)m;
            float a = sqrtf((4.0f * dl * dl - 1.0f) / (dl * dl - dm * dm));
            float b = sqrtf(((dl - 1.0f) * (dl - 1.0f) - dm * dm) /
                            (4.0f * (dl - 1.0f) * (dl - 1.0f) - 1.0f));
            float p = a * (ct * pl1 - b * pl0);
            float pw2 = p * w;
            bf16split(pw2, h, l);
            g_Wh[((size_t)m * LMAX + ll) * 256 + k] = h;  g_Wl[((size_t)m * LMAX + ll) * 256 + k] = l;
            bf16split(p, h, l);
            g_Ph[((size_t)m * 256 + k) * LMAX + ll] = h;  g_Pl[((size_t)m * 256 + k) * LMAX + ll] = l;
            pl0 = pl1; pl1 = p;
        }
    }
}

__global__ void k_init_dft() {
    int a = blockIdx.x, b = threadIdx.x;
    __nv_bfloat16 h, l;
    {   int m = a >> 1, ri = a & 1;
        float th = 2.0f * (float)PI_D * (float)((m * b) & 255) / 256.0f;
        float s = 2.0f * (float)PI_D / 256.0f;
        float v = ri ? -s * sinf(th) : s * cosf(th);
        bf16split(v, h, l);
        g_Dh[a * 256 + b] = h;  g_Dl[a * 256 + b] = l;
    }
    {   int m = b >> 1, ri = b & 1;
        float th = 2.0f * (float)PI_D * (float)((m * a) & 255) / 256.0f;
        float cm = (m == 0) ? 1.0f : 2.0f;
        float v = ri ? -cm * sinf(th) : cm * cosf(th);
        bf16split(v, h, l);
        g_Ih[a * 256 + b] = h;  g_Il[a * 256 + b] = l;
    }
}

// ---------------- double-buffered warp-MMA split-bf16 GEMM ------------------------
// C tile[128x128] = A * B^T.  A fp32 row-major [M x K] (or transA: [K x M], ld=M).
// B [N][K] K-major bf16 hi/lo.  3-term split into fp32 acc.
// transC: write C^T (dst [N_total][M_total]) via smem staging, coalesced.
#define BUFB 40960           // one pipeline buffer: Ah,Al,Bh,Bl (each 128*40*2 B)
#define GDSM (2*BUFB)

__global__ void __launch_bounds__(256) k_gemm(
    const float* __restrict__ A, size_t sA, int lda,
    const __nv_bfloat16* __restrict__ Bh, const __nv_bfloat16* __restrict__ Bl, size_t sB,
    float* __restrict__ C, size_t sC, int ldc, int K, int tri, int transA, int transC)
{
    extern __shared__ char dsm[];
    int tid = threadIdx.x, lane = tid & 31, wid = tid >> 5;
    int z = blockIdx.z;
    A  += sA * z;  Bh += sB * z;  Bl += sB * z;  C += sC * z;
    size_t row0 = (size_t)blockIdx.x * 128;
    int col0 = blockIdx.y * 128;
    int wm = wid & 3, wn = wid >> 2;

    float acc[2][8][4] = {};

    int a_row = (lane & 7) + ((lane >> 3) & 1) * 8;
    int a_ko  = (lane >> 4) * 8;
    int b_row = (lane & 7) + ((lane >> 4) & 1) * 8;
    int b_ko  = ((lane >> 3) & 1) * 8;

    unsigned sbase = smem_u32(dsm);
    int kb = tri ? (z & ~31) : 0;
    int nch = (K - kb) >> 5;

    auto ldA = [&](int k0, float4 (&av)[4]) {
#pragma unroll
        for (int rp = 0; rp < 4; rp++) {
            int idx = rp * 256 + tid;
            if (!transA) {
                int r = idx >> 3, kq = idx & 7;
                av[rp] = *(const float4*)(A + (row0 + r) * lda + k0 + kq * 4);
            } else {
                int k = idx >> 5, rq = idx & 31;
                av[rp] = *(const float4*)(A + (size_t)(k0 + k) * lda + row0 + rq * 4);
            }
        }
    };
    auto stA = [&](char* buf, float4 (&av)[4]) {
#pragma unroll
        for (int rp = 0; rp < 4; rp++) {
            int idx = rp * 256 + tid;
            __nv_bfloat16 h0, h1, h2, h3, l0, l1, l2, l3;
            bf16split(av[rp].x, h0, l0); bf16split(av[rp].y, h1, l1);
            bf16split(av[rp].z, h2, l2); bf16split(av[rp].w, h3, l3);
            if (!transA) {
                int r = idx >> 3, kq = idx & 7;
                uint2 hh; hh.x = pk(h0, h1); hh.y = pk(h2, h3);
                uint2 ll; ll.x = pk(l0, l1); ll.y = pk(l2, l3);
                *(uint2*)(buf +         r * 80 + kq * 8) = hh;
                *(uint2*)(buf + 10240 + r * 80 + kq * 8) = ll;
            } else {
                int k = idx >> 5, rq = idx & 31;
                __nv_bfloat16 hs[4] = {h0, h1, h2, h3}, ls[4] = {l0, l1, l2, l3};
#pragma unroll
                for (int e = 0; e < 4; e++) {
                    *(__nv_bfloat16*)(buf +         (rq * 4 + e) * 80 + k * 2) = hs[e];
                    *(__nv_bfloat16*)(buf + 10240 + (rq * 4 + e) * 80 + k * 2) = ls[e];
                }
            }
        }
    };
    auto ldB = [&](int k0, unsigned bufu) {
#pragma unroll
        for (int rp = 0; rp < 2; rp++) {
            int idx = rp * 256 + tid;
            int r = idx >> 2, q = idx & 3;
            const void* gh = (const void*)(Bh + (size_t)(col0 + r) * K + k0 + q * 8);
            const void* gl = (const void*)(Bl + (size_t)(col0 + r) * K + k0 + q * 8);
            unsigned sh = bufu + 20480 + r * 80 + q * 16;
            unsigned sl = bufu + 30720 + r * 80 + q * 16;
            asm volatile("cp.async.ca.shared.global [%0], [%1], 16;" :: "r"(sh), "l"(gh));
            asm volatile("cp.async.ca.shared.global [%0], [%1], 16;" :: "r"(sl), "l"(gl));
        }
        asm volatile("cp.async.commit_group;" ::: "memory");
    };
    auto compute = [&](unsigned bufu) {
        unsigned uAh = bufu, uAl = bufu + 10240, uBh = bufu + 20480, uBl = bufu + 30720;
#pragma unroll
        for (int s = 0; s < 2; s++) {
            unsigned ah[2][4], al[2][4];
#pragma unroll
            for (int mt = 0; mt < 2; mt++) {
                unsigned off = (unsigned)((wm * 32 + mt * 16 + a_row) * 80 + (s * 16 + a_ko) * 2);
                LDSM4(ah[mt][0], ah[mt][1], ah[mt][2], ah[mt][3], uAh + off);
                LDSM4(al[mt][0], al[mt][1], al[mt][2], al[mt][3], uAl + off);
            }
#pragma unroll
            for (int nt = 0; nt < 4; nt++) {
                unsigned off = (unsigned)((wn * 64 + nt * 16 + b_row) * 80 + (s * 16 + b_ko) * 2);
                unsigned bh0, bh1, bh2, bh3, bl0, bl1, bl2, bl3;
                LDSM4(bh0, bh1, bh2, bh3, uBh + off);
                LDSM4(bl0, bl1, bl2, bl3, uBl + off);
#pragma unroll
                for (int mt = 0; mt < 2; mt++) {
                    MMA16816(acc[mt][2 * nt],     ah[mt], bh0, bh1);
                    MMA16816(acc[mt][2 * nt + 1], ah[mt], bh2, bh3);
                    MMA16816(acc[mt][2 * nt],     ah[mt], bl0, bl1);
                    MMA16816(acc[mt][2 * nt + 1], ah[mt], bl2, bl3);
                    MMA16816(acc[mt][2 * nt],     al[mt], bh0, bh1);
                    MMA16816(acc[mt][2 * nt + 1], al[mt], bh2, bh3);
                }
            }
        }
    };

    // prologue: fill buffer 0
    {
        float4 av[4];
        ldA(kb, av);
        ldB(kb, sbase);
        stA(dsm, av);
        asm volatile("cp.async.wait_group 0;" ::: "memory");
        __syncthreads();
    }
    int cur = 0;
    for (int t = 0; t < nch; t++) {
        float4 av[4];
        bool has = (t + 1 < nch);
        if (has) {
            ldA(kb + (t + 1) * 32, av);
            ldB(kb + (t + 1) * 32, sbase + (cur ^ 1) * BUFB);
        }
        compute(sbase + cur * BUFB);
        if (has) {
            stA(dsm + (cur ^ 1) * BUFB, av);
            asm volatile("cp.async.wait_group 0;" ::: "memory");
        }
        __syncthreads();
        cur ^= 1;
    }

    // ---- epilogue
    int g = lane >> 2, tt = lane & 3;
    if (!transC) {
#pragma unroll
        for (int mt = 0; mt < 2; mt++)
#pragma unroll
            for (int ntq = 0; ntq < 8; ntq++) {
                float* base = C + (row0 + wm * 32 + mt * 16 + g) * ldc
                                + col0 + wn * 64 + ntq * 8 + tt * 2;
                float2 v0; v0.x = acc[mt][ntq][0]; v0.y = acc[mt][ntq][1];
                float2 v1; v1.x = acc[mt][ntq][2]; v1.y = acc[mt][ntq][3];
                *(float2*)base = v0;
                *(float2*)(base + 8 * (size_t)ldc) = v1;
            }
    } else {
        // stage C^T in smem (64 cols x 128 rows, pitch 132 floats), write coalesced
        float* st = (float*)dsm;
#pragma unroll 1
        for (int half = 0; half < 2; half++) {
            __syncthreads();
            if (wn == half) {
#pragma unroll
                for (int mt = 0; mt < 2; mt++)
#pragma unroll
                    for (int ntq = 0; ntq < 8; ntq++) {
                        int lc = ntq * 8 + tt * 2;
                        int rl = wm * 32 + mt * 16 + g;
                        st[lc * 132 + rl]           = acc[mt][ntq][0];
                        st[(lc + 1) * 132 + rl]     = acc[mt][ntq][1];
                        st[lc * 132 + rl + 8]       = acc[mt][ntq][2];
                        st[(lc + 1) * 132 + rl + 8] = acc[mt][ntq][3];
                    }
            }
            __syncthreads();
#pragma unroll
            for (int it = 0; it < 8; it++) {
                int flat = it * 256 + tid;
                int cc = flat >> 5, rq = flat & 31;
                float4 v = *(float4*)(st + cc * 132 + rq * 4);
                *(float4*)(C + (size_t)(col0 + half * 64 + cc) * ldc + row0 + rq * 4) = v;
            }
        }
    }
}

// ---------------- transpose: src[R][C_] -> dst[C_][R] ----------------
__global__ void k_tr(const float* __restrict__ src, float* __restrict__ dst, int R, int C_) {
    __shared__ float t[32][33];
    int c0 = blockIdx.x * 32, r0 = blockIdx.y * 32;
    for (int i = threadIdx.y; i < 32; i += 8)
        t[i][threadIdx.x] = src[(size_t)(r0 + i) * C_ + c0 + threadIdx.x];
    __syncthreads();
    for (int i = threadIdx.y; i < 32; i += 8)
        dst[(size_t)(c0 + i) * R + r0 + threadIdx.x] = t[threadIdx.x][i];
}

// ---------------- per-coefficient channel mix ----------------
__global__ __launch_bounds__(256) void k_mix(const float* __restrict__ w) {
    int l = blockIdx.y;
    int jt = blockIdx.x;
    if (jt * 16 > l) return;
    int j0 = jt * 32;
    __shared__ float ws[32 * 33];
    __shared__ float ss[8 * 32];
    int tid = threadIdx.x;
    int o = tid >> 3, jg = tid & 7;
    float acc[4][8] = {};
    for (int i = 0; i < CIN; i++) {
        __syncthreads();
        for (int t = tid; t < 1024; t += 256) {
            int oo = t >> 5, jj = t & 31;
            ws[oo * 33 + jj] = w[(size_t)(i * COUT + oo) * XSTRIDE + l * 258 + j0 + jj];
        }
        { int b = tid >> 5, jj = tid & 31;
          ss[b * 32 + jj] = g_spec[((size_t)(b * CIN + i) * LMAX + l) * J2 + j0 + jj]; }
        __syncthreads();
#pragma unroll
        for (int q = 0; q < 4; q++) {
            float wv = ws[o * 33 + jg + 8 * q];
#pragma unroll
            for (int b = 0; b < 8; b++)
                acc[q][b] += ss[b * 32 + jg + 8 * q] * wv;
        }
    }
#pragma unroll
    for (int q = 0; q < 4; q++)
#pragma unroll
        for (int b = 0; b < 8; b++)
            g_ospec[((size_t)(b * COUT + o) * LMAX + l) * J2 + j0 + jg + 8 * q] = acc[q][b];
}

// ---------------- launcher ----------------
extern "C" void kernel_launch(void* const* d_in, const int* in_sizes, int n_in,
                              void* d_out, int out_size) {
    const float* x = (const float*)d_in[0];
    const float* w = (const float*)d_in[1];
    if (n_in >= 2 && in_sizes[0] != BATCH * CIN * NLAT * NLON) {
        const float* t = x; x = w; w = t;
    }
    float* y = (float*)d_out;

    cudaFuncSetAttribute(k_gemm, cudaFuncAttributeMaxDynamicSharedMemorySize, GDSM);

    void *pDh, *pDl, *pIh, *pIl, *pWh, *pWl, *pPh, *pPl;
    void *pF, *pCF, *pT, *pG, *pSpec, *pOspec;
    cudaGetSymbolAddress(&pDh, g_Dh);  cudaGetSymbolAddress(&pDl, g_Dl);
    cudaGetSymbolAddress(&pIh, g_Ih);  cudaGetSymbolAddress(&pIl, g_Il);
    cudaGetSymbolAddress(&pWh, g_Wh);  cudaGetSymbolAddress(&pWl, g_Wl);
    cudaGetSymbolAddress(&pPh, g_Ph);  cudaGetSymbolAddress(&pPl, g_Pl);
    cudaGetSymbolAddress(&pF, g_F);    cudaGetSymbolAddress(&pCF, g_CF);
    cudaGetSymbolAddress(&pT, g_T);    cudaGetSymbolAddress(&pG, g_G);
    cudaGetSymbolAddress(&pSpec, g_spec); cudaGetSymbolAddress(&pOspec, g_ospec);

    k_init_w  <<<1, 256>>>();
    k_init_P  <<<128, 256>>>();
    k_init_dft<<<256, 256>>>();

    // 1) fwd DFT with fused transpose: g_F[j][(bc,k)] = (x * D^T)^T
    k_gemm<<<dim3(512, 2, 1), 256, GDSM>>>(
        x, 0, NLON, (const __nv_bfloat16*)pDh, (const __nv_bfloat16*)pDl, 0,
        (float*)pF, 0, ROWS_X, 256, 0, 0, 1);

    // 2) fwd Legendre per m: g_CF[2m..][sr][l] = F_slab * W[m]^T
    k_gemm<<<dim3(4, 1, 128), 256, GDSM>>>(
        (const float*)pF, (size_t)2 * ROWS_X, NLAT,
        (const __nv_bfloat16*)pWh, (const __nv_bfloat16*)pWl, (size_t)128 * 256,
        (float*)pCF, (size_t)2 * ROWS_L, LMAX, 256, 0, 0, 0);

    // 3) transpose -> spec layout for mix
    k_tr<<<dim3(1024, 8), dim3(32, 8)>>>((const float*)pCF, (float*)pSpec, 256, ROWS_L);

    // 4) channel mix
    k_mix<<<dim3(8, LMAX), 256>>>(w);

    // 5) transpose back
    k_tr<<<dim3(8, 1024), dim3(32, 8)>>>((const float*)pOspec, (float*)pT, ROWS_L, 256);

    // 6) inv Legendre per m (triangular K-skip): g_G[2m..][sr][k] = T_slab * P[m]^T
    k_gemm<<<dim3(4, 2, 128), 256, GDSM>>>(
        (const float*)pT, (size_t)2 * ROWS_L, LMAX,
        (const __nv_bfloat16*)pPh, (const __nv_bfloat16*)pPl, (size_t)256 * 128,
        (float*)pG, (size_t)2 * ROWS_X, NLAT, 128, 1, 0, 0);

    // 8) inv DFT reading A transposed in place: y[(bo,k)][n] = G^T * I^T
    k_gemm<<<dim3(512, 2, 1), 256, GDSM>>>(
        (const float*)pG, 0, ROWS_X, (const __nv_bfloat16*)pIh, (const __nv_bfloat16*)pIl, 0,
        y, 0, 256, 256, 0, 1, 0);
}